// round 2
// baseline (speedup 1.0000x reference)
#include <cuda_runtime.h>

#define BB 4
#define CC 64
#define HH 256
#define WW 256
#define HW (HH*WW)
#define CHW (CC*HW)

#define SIGMA_MIN 0.6f
#define SIGMA_MAX 1.2f

// Scratch (static device allocations — no cudaMalloc allowed)
__device__ float d_edge[BB*HW];          // 1 MB
__device__ float d_g[4][BB*HW];          // 4 MB (symmetric taps: w0,w1,w2,center)
__device__ float d_tmp[(size_t)BB*CHW];  // 64 MB horizontal-pass result
__device__ unsigned int d_minmax[2*BB];  // per-batch {min,max} as uint bits (edge>=0)

__global__ void init_minmax_kernel() {
    int i = threadIdx.x;
    if (i < BB) {
        d_minmax[2*i]   = 0x7f800000u; // +inf
        d_minmax[2*i+1] = 0u;          // 0
    }
}

// Sobel edge magnitude, mean over channels; fused per-batch min/max reduction.
// Block = (64,4): full-width 256x4 tile, float4 loads, separable Sobel.
__global__ __launch_bounds__(256) void edge_kernel(const float* __restrict__ x) {
    __shared__ float xs[6][264];           // rows h0-1..h0+4, cols: data at [4..259], zero halo at [3],[260]
    __shared__ float smin[8], smax[8];

    const int tx = threadIdx.x;            // 0..63 (column quad)
    const int ty = threadIdx.y;            // 0..3  (row in tile)
    const int tid = ty*64 + tx;
    const int h0 = blockIdx.x*4;
    const int b  = blockIdx.y;

    if (tid < 6) { xs[tid][3] = 0.f; xs[tid][260] = 0.f; }

    const float* xb = x + (size_t)b*CHW;
    float acc[4] = {0.f, 0.f, 0.f, 0.f};

    for (int c = 0; c < CC; c++) {
        __syncthreads();
        // stage 6 rows x 256 cols = 384 float4 with 256 threads
        #pragma unroll
        for (int k = 0; k < 2; k++) {
            int i = tid + k*256;
            if (i < 384) {
                int r = i >> 6, c4 = i & 63;
                int gh = h0 - 1 + r;
                float4 v = make_float4(0.f, 0.f, 0.f, 0.f);
                if (gh >= 0 && gh < HH)
                    v = *(const float4*)(xb + (size_t)c*HW + gh*WW + c4*4);
                *(float4*)&xs[r][4 + c4*4] = v;
            }
        }
        __syncthreads();

        float d[3][4], s[3][4];
        #pragma unroll
        for (int r = 0; r < 3; r++) {
            const float* row = &xs[ty + r][4 + 4*tx];
            float  l = row[-1];
            float4 m = *(const float4*)row;
            float rr = row[4];
            d[r][0] = m.y - l;    s[r][0] = l   + 2.f*m.x + m.y;
            d[r][1] = m.z - m.x;  s[r][1] = m.x + 2.f*m.y + m.z;
            d[r][2] = m.w - m.y;  s[r][2] = m.y + 2.f*m.z + m.w;
            d[r][3] = rr  - m.z;  s[r][3] = m.z + 2.f*m.w + rr;
        }
        #pragma unroll
        for (int j = 0; j < 4; j++) {
            float gx = d[0][j] + 2.f*d[1][j] + d[2][j];
            float gy = s[2][j] - s[0][j];
            acc[j] = fmaf(gx, gx, acc[j]);
            acc[j] = fmaf(gy, gy, acc[j]);
        }
    }

    float4 e;
    e.x = acc[0]*(1.f/64.f); e.y = acc[1]*(1.f/64.f);
    e.z = acc[2]*(1.f/64.f); e.w = acc[3]*(1.f/64.f);
    *(float4*)(d_edge + b*HW + (h0+ty)*WW + 4*tx) = e;

    // block min/max -> atomics (uint ordering valid for non-negative floats)
    float vmin = fminf(fminf(e.x, e.y), fminf(e.z, e.w));
    float vmax = fmaxf(fmaxf(e.x, e.y), fmaxf(e.z, e.w));
    #pragma unroll
    for (int o = 16; o; o >>= 1) {
        vmin = fminf(vmin, __shfl_xor_sync(0xffffffffu, vmin, o));
        vmax = fmaxf(vmax, __shfl_xor_sync(0xffffffffu, vmax, o));
    }
    const int wid = tid >> 5, lane = tid & 31;
    if (lane == 0) { smin[wid] = vmin; smax[wid] = vmax; }
    __syncthreads();
    if (tid == 0) {
        float m = smin[0], M = smax[0];
        #pragma unroll
        for (int i = 1; i < 8; i++) { m = fminf(m, smin[i]); M = fmaxf(M, smax[i]); }
        atomicMin(&d_minmax[2*b],   __float_as_uint(m));
        atomicMax(&d_minmax[2*b+1], __float_as_uint(M));
    }
}

// Per-pixel normalized Gaussian taps (symmetric: store 4 planes).
__global__ void gauss_kernel() {
    const int idx = blockIdx.x*blockDim.x + threadIdx.x;
    const int b = idx / HW;
    const float emin = __uint_as_float(d_minmax[2*b]);
    const float emax = __uint_as_float(d_minmax[2*b+1]);
    const float e = (d_edge[idx] - emin) / (emax + 1e-6f);
    const float s = SIGMA_MIN + (SIGMA_MAX - SIGMA_MIN)*e;
    const float inv = 0.5f / (s*s);
    const float w2 = __expf(-1.f*inv);
    const float w1 = __expf(-4.f*inv);
    const float w0 = __expf(-9.f*inv);
    const float r = 1.f / (2.f*(w0 + w1 + w2) + 1.f);
    d_g[0][idx] = w0*r;
    d_g[1][idx] = w1*r;
    d_g[2][idx] = w2*r;
    d_g[3][idx] = r;
}

// Horizontal pass: thread = 4 outputs, g in regs across channel loop, no barriers.
__global__ __launch_bounds__(256) void hblur_kernel(const float* __restrict__ x) {
    const int tx = threadIdx.x;                 // 0..63
    const int h  = blockIdx.x*4 + threadIdx.y;
    const int b  = blockIdx.y;
    const int w4 = tx*4;
    const int pidx = b*HW + h*WW + w4;

    const float4 G0 = *(const float4*)&d_g[0][pidx];
    const float4 G1 = *(const float4*)&d_g[1][pidx];
    const float4 G2 = *(const float4*)&d_g[2][pidx];
    const float4 G3 = *(const float4*)&d_g[3][pidx];

    const float* xr = x     + (size_t)b*CHW + h*WW + w4;
    float*       tr = d_tmp + (size_t)b*CHW + h*WW + w4;
    const bool hasL = (tx > 0), hasR = (tx < 63);
    const float4 z4 = make_float4(0.f, 0.f, 0.f, 0.f);

    #pragma unroll 2
    for (int c = 0; c < CC; c++) {
        const float* p = xr + (size_t)c*HW;
        float4 m  = *(const float4*)p;
        float4 lf = hasL ? *(const float4*)(p - 4) : z4;
        float4 rf = hasR ? *(const float4*)(p + 4) : z4;
        // v[0..9] = x[w-3..w+6]
        float v0=lf.y, v1=lf.z, v2=lf.w, v3=m.x, v4=m.y, v5=m.z, v6=m.w, v7=rf.x, v8=rf.y, v9=rf.z;
        float4 o;
        o.x = fmaf(G0.x, v0+v6, fmaf(G1.x, v1+v5, fmaf(G2.x, v2+v4, G3.x*v3)));
        o.y = fmaf(G0.y, v1+v7, fmaf(G1.y, v2+v6, fmaf(G2.y, v3+v5, G3.y*v4)));
        o.z = fmaf(G0.z, v2+v8, fmaf(G1.z, v3+v7, fmaf(G2.z, v4+v6, G3.z*v5)));
        o.w = fmaf(G0.w, v3+v9, fmaf(G1.w, v4+v8, fmaf(G2.w, v5+v7, G3.w*v6)));
        *(float4*)(tr + (size_t)c*HW) = o;
    }
}

// Vertical pass: thread = 4 outputs, 7 guarded row loads (tmp is L2-resident).
__global__ __launch_bounds__(256) void vblur_kernel(float* __restrict__ out) {
    const int tx = threadIdx.x;
    const int h  = blockIdx.x*4 + threadIdx.y;
    const int b  = blockIdx.y;
    const int w4 = tx*4;
    const int pidx = b*HW + h*WW + w4;

    const float4 G0 = *(const float4*)&d_g[0][pidx];
    const float4 G1 = *(const float4*)&d_g[1][pidx];
    const float4 G2 = *(const float4*)&d_g[2][pidx];
    const float4 G3 = *(const float4*)&d_g[3][pidx];

    const float* tp = d_tmp + (size_t)b*CHW + h*WW + w4;
    float*       op = out   + (size_t)b*CHW + h*WW + w4;

    const bool m1 = (h >= 1), m2 = (h >= 2), m3 = (h >= 3);
    const bool p1 = (h < HH-1), p2 = (h < HH-2), p3 = (h < HH-3);
    const float4 z4 = make_float4(0.f, 0.f, 0.f, 0.f);

    #pragma unroll 2
    for (int c = 0; c < CC; c++) {
        const float* p = tp + (size_t)c*HW;
        float4 cm = *(const float4*)p;
        float4 u1 = m1 ? *(const float4*)(p -   WW) : z4;
        float4 d1 = p1 ? *(const float4*)(p +   WW) : z4;
        float4 u2 = m2 ? *(const float4*)(p - 2*WW) : z4;
        float4 d2 = p2 ? *(const float4*)(p + 2*WW) : z4;
        float4 u3 = m3 ? *(const float4*)(p - 3*WW) : z4;
        float4 d3 = p3 ? *(const float4*)(p + 3*WW) : z4;
        float4 o;
        o.x = fmaf(G0.x, u3.x+d3.x, fmaf(G1.x, u2.x+d2.x, fmaf(G2.x, u1.x+d1.x, G3.x*cm.x)));
        o.y = fmaf(G0.y, u3.y+d3.y, fmaf(G1.y, u2.y+d2.y, fmaf(G2.y, u1.y+d1.y, G3.y*cm.y)));
        o.z = fmaf(G0.z, u3.z+d3.z, fmaf(G1.z, u2.z+d2.z, fmaf(G2.z, u1.z+d1.z, G3.z*cm.z)));
        o.w = fmaf(G0.w, u3.w+d3.w, fmaf(G1.w, u2.w+d2.w, fmaf(G2.w, u1.w+d1.w, G3.w*cm.w)));
        *(float4*)(op + (size_t)c*HW) = o;
    }
}

extern "C" void kernel_launch(void* const* d_in, const int* in_sizes, int n_in,
                              void* d_out, int out_size) {
    const float* x = (const float*)d_in[0];
    float* out = (float*)d_out;

    init_minmax_kernel<<<1, 32>>>();

    dim3 blk(64, 4);
    edge_kernel<<<dim3(HH/4, BB), blk>>>(x);

    gauss_kernel<<<(BB*HW)/256, 256>>>();

    hblur_kernel<<<dim3(HH/4, BB), blk>>>(x);

    vblur_kernel<<<dim3(HH/4, BB), blk>>>(out);
}

// round 3
// speedup vs baseline: 1.0079x; 1.0079x over previous
#include <cuda_runtime.h>

#define BB 4
#define CC 64
#define HH 256
#define WW 256
#define HW (HH*WW)
#define CHW (CC*HW)

#define SIGMA_MIN 0.6f
#define SIGMA_MAX 1.2f

// Scratch (static device allocations — no cudaMalloc allowed)
__device__ float d_edge[BB*HW];          // 1 MB
__device__ float d_g[4][BB*HW];          // 4 MB (symmetric taps: w0,w1,w2,center)
__device__ float d_tmp[(size_t)BB*CHW];  // 64 MB horizontal-pass result
__device__ unsigned int d_minmax[2*BB];  // per-batch {min,max} as uint bits (edge>=0)

__global__ void init_minmax_kernel() {
    int i = threadIdx.x;
    if (i < BB) {
        d_minmax[2*i]   = 0x7f800000u; // +inf
        d_minmax[2*i+1] = 0u;          // 0
    }
}

// Sobel edge magnitude, mean over channels; fused per-batch min/max reduction.
// Block = (64,4): full-width 256x4 tile, float4 loads, separable Sobel.
__global__ __launch_bounds__(256) void edge_kernel(const float* __restrict__ x) {
    __shared__ float xs[6][264];           // rows h0-1..h0+4, cols: data at [4..259], zero halo at [3],[260]
    __shared__ float smin[8], smax[8];

    const int tx = threadIdx.x;            // 0..63 (column quad)
    const int ty = threadIdx.y;            // 0..3  (row in tile)
    const int tid = ty*64 + tx;
    const int h0 = blockIdx.x*4;
    const int b  = blockIdx.y;

    if (tid < 6) { xs[tid][3] = 0.f; xs[tid][260] = 0.f; }

    const float* xb = x + (size_t)b*CHW;
    float acc[4] = {0.f, 0.f, 0.f, 0.f};

    for (int c = 0; c < CC; c++) {
        __syncthreads();
        // stage 6 rows x 256 cols = 384 float4 with 256 threads
        #pragma unroll
        for (int k = 0; k < 2; k++) {
            int i = tid + k*256;
            if (i < 384) {
                int r = i >> 6, c4 = i & 63;
                int gh = h0 - 1 + r;
                float4 v = make_float4(0.f, 0.f, 0.f, 0.f);
                if (gh >= 0 && gh < HH)
                    v = *(const float4*)(xb + (size_t)c*HW + gh*WW + c4*4);
                *(float4*)&xs[r][4 + c4*4] = v;
            }
        }
        __syncthreads();

        float d[3][4], s[3][4];
        #pragma unroll
        for (int r = 0; r < 3; r++) {
            const float* row = &xs[ty + r][4 + 4*tx];
            float  l = row[-1];
            float4 m = *(const float4*)row;
            float rr = row[4];
            d[r][0] = m.y - l;    s[r][0] = l   + 2.f*m.x + m.y;
            d[r][1] = m.z - m.x;  s[r][1] = m.x + 2.f*m.y + m.z;
            d[r][2] = m.w - m.y;  s[r][2] = m.y + 2.f*m.z + m.w;
            d[r][3] = rr  - m.z;  s[r][3] = m.z + 2.f*m.w + rr;
        }
        #pragma unroll
        for (int j = 0; j < 4; j++) {
            float gx = d[0][j] + 2.f*d[1][j] + d[2][j];
            float gy = s[2][j] - s[0][j];
            acc[j] = fmaf(gx, gx, acc[j]);
            acc[j] = fmaf(gy, gy, acc[j]);
        }
    }

    float4 e;
    e.x = acc[0]*(1.f/64.f); e.y = acc[1]*(1.f/64.f);
    e.z = acc[2]*(1.f/64.f); e.w = acc[3]*(1.f/64.f);
    *(float4*)(d_edge + b*HW + (h0+ty)*WW + 4*tx) = e;

    // block min/max -> atomics (uint ordering valid for non-negative floats)
    float vmin = fminf(fminf(e.x, e.y), fminf(e.z, e.w));
    float vmax = fmaxf(fmaxf(e.x, e.y), fmaxf(e.z, e.w));
    #pragma unroll
    for (int o = 16; o; o >>= 1) {
        vmin = fminf(vmin, __shfl_xor_sync(0xffffffffu, vmin, o));
        vmax = fmaxf(vmax, __shfl_xor_sync(0xffffffffu, vmax, o));
    }
    const int wid = tid >> 5, lane = tid & 31;
    if (lane == 0) { smin[wid] = vmin; smax[wid] = vmax; }
    __syncthreads();
    if (tid == 0) {
        float m = smin[0], M = smax[0];
        #pragma unroll
        for (int i = 1; i < 8; i++) { m = fminf(m, smin[i]); M = fmaxf(M, smax[i]); }
        atomicMin(&d_minmax[2*b],   __float_as_uint(m));
        atomicMax(&d_minmax[2*b+1], __float_as_uint(M));
    }
}

// Per-pixel normalized Gaussian taps (symmetric: store 4 planes).
__global__ void gauss_kernel() {
    const int idx = blockIdx.x*blockDim.x + threadIdx.x;
    const int b = idx / HW;
    const float emin = __uint_as_float(d_minmax[2*b]);
    const float emax = __uint_as_float(d_minmax[2*b+1]);
    const float e = (d_edge[idx] - emin) / (emax + 1e-6f);
    const float s = SIGMA_MIN + (SIGMA_MAX - SIGMA_MIN)*e;
    const float inv = 0.5f / (s*s);
    const float w2 = __expf(-1.f*inv);
    const float w1 = __expf(-4.f*inv);
    const float w0 = __expf(-9.f*inv);
    const float r = 1.f / (2.f*(w0 + w1 + w2) + 1.f);
    d_g[0][idx] = w0*r;
    d_g[1][idx] = w1*r;
    d_g[2][idx] = w2*r;
    d_g[3][idx] = r;
}

// Horizontal pass: thread = 4 outputs, g in regs across channel loop, no barriers.
__global__ __launch_bounds__(256) void hblur_kernel(const float* __restrict__ x) {
    const int tx = threadIdx.x;                 // 0..63
    const int h  = blockIdx.x*4 + threadIdx.y;
    const int b  = blockIdx.y;
    const int w4 = tx*4;
    const int pidx = b*HW + h*WW + w4;

    const float4 G0 = *(const float4*)&d_g[0][pidx];
    const float4 G1 = *(const float4*)&d_g[1][pidx];
    const float4 G2 = *(const float4*)&d_g[2][pidx];
    const float4 G3 = *(const float4*)&d_g[3][pidx];

    const float* xr = x     + (size_t)b*CHW + h*WW + w4;
    float*       tr = d_tmp + (size_t)b*CHW + h*WW + w4;
    const bool hasL = (tx > 0), hasR = (tx < 63);
    const float4 z4 = make_float4(0.f, 0.f, 0.f, 0.f);

    #pragma unroll 2
    for (int c = 0; c < CC; c++) {
        const float* p = xr + (size_t)c*HW;
        float4 m  = *(const float4*)p;
        float4 lf = hasL ? *(const float4*)(p - 4) : z4;
        float4 rf = hasR ? *(const float4*)(p + 4) : z4;
        // v[0..9] = x[w-3..w+6]
        float v0=lf.y, v1=lf.z, v2=lf.w, v3=m.x, v4=m.y, v5=m.z, v6=m.w, v7=rf.x, v8=rf.y, v9=rf.z;
        float4 o;
        o.x = fmaf(G0.x, v0+v6, fmaf(G1.x, v1+v5, fmaf(G2.x, v2+v4, G3.x*v3)));
        o.y = fmaf(G0.y, v1+v7, fmaf(G1.y, v2+v6, fmaf(G2.y, v3+v5, G3.y*v4)));
        o.z = fmaf(G0.z, v2+v8, fmaf(G1.z, v3+v7, fmaf(G2.z, v4+v6, G3.z*v5)));
        o.w = fmaf(G0.w, v3+v9, fmaf(G1.w, v4+v8, fmaf(G2.w, v5+v7, G3.w*v6)));
        *(float4*)(tr + (size_t)c*HW) = o;
    }
}

// Vertical pass: thread = 4 outputs, 7 guarded row loads (tmp is L2-resident).
__global__ __launch_bounds__(256) void vblur_kernel(float* __restrict__ out) {
    const int tx = threadIdx.x;
    const int h  = blockIdx.x*4 + threadIdx.y;
    const int b  = blockIdx.y;
    const int w4 = tx*4;
    const int pidx = b*HW + h*WW + w4;

    const float4 G0 = *(const float4*)&d_g[0][pidx];
    const float4 G1 = *(const float4*)&d_g[1][pidx];
    const float4 G2 = *(const float4*)&d_g[2][pidx];
    const float4 G3 = *(const float4*)&d_g[3][pidx];

    const float* tp = d_tmp + (size_t)b*CHW + h*WW + w4;
    float*       op = out   + (size_t)b*CHW + h*WW + w4;

    const bool m1 = (h >= 1), m2 = (h >= 2), m3 = (h >= 3);
    const bool p1 = (h < HH-1), p2 = (h < HH-2), p3 = (h < HH-3);
    const float4 z4 = make_float4(0.f, 0.f, 0.f, 0.f);

    #pragma unroll 2
    for (int c = 0; c < CC; c++) {
        const float* p = tp + (size_t)c*HW;
        float4 cm = *(const float4*)p;
        float4 u1 = m1 ? *(const float4*)(p -   WW) : z4;
        float4 d1 = p1 ? *(const float4*)(p +   WW) : z4;
        float4 u2 = m2 ? *(const float4*)(p - 2*WW) : z4;
        float4 d2 = p2 ? *(const float4*)(p + 2*WW) : z4;
        float4 u3 = m3 ? *(const float4*)(p - 3*WW) : z4;
        float4 d3 = p3 ? *(const float4*)(p + 3*WW) : z4;
        float4 o;
        o.x = fmaf(G0.x, u3.x+d3.x, fmaf(G1.x, u2.x+d2.x, fmaf(G2.x, u1.x+d1.x, G3.x*cm.x)));
        o.y = fmaf(G0.y, u3.y+d3.y, fmaf(G1.y, u2.y+d2.y, fmaf(G2.y, u1.y+d1.y, G3.y*cm.y)));
        o.z = fmaf(G0.z, u3.z+d3.z, fmaf(G1.z, u2.z+d2.z, fmaf(G2.z, u1.z+d1.z, G3.z*cm.z)));
        o.w = fmaf(G0.w, u3.w+d3.w, fmaf(G1.w, u2.w+d2.w, fmaf(G2.w, u1.w+d1.w, G3.w*cm.w)));
        *(float4*)(op + (size_t)c*HW) = o;
    }
}

extern "C" void kernel_launch(void* const* d_in, const int* in_sizes, int n_in,
                              void* d_out, int out_size) {
    const float* x = (const float*)d_in[0];
    float* out = (float*)d_out;

    init_minmax_kernel<<<1, 32>>>();

    dim3 blk(64, 4);
    edge_kernel<<<dim3(HH/4, BB), blk>>>(x);

    gauss_kernel<<<(BB*HW)/256, 256>>>();

    hblur_kernel<<<dim3(HH/4, BB), blk>>>(x);

    vblur_kernel<<<dim3(HH/4, BB), blk>>>(out);
}

// round 4
// speedup vs baseline: 1.6963x; 1.6830x over previous
#include <cuda_runtime.h>

#define BB 4
#define CC 64
#define HH 256
#define WW 256
#define HW (HH*WW)
#define CHW (CC*HW)

#define NSPLIT 8
#define ECH (CC/NSPLIT)   // 8 channels per edge block
#define BCH 8             // channels per blur block

#define SIGMA_MIN 0.6f
#define SIGMA_MAX 1.2f

// Scratch (static device allocations — no cudaMalloc allowed)
__device__ float d_edge[BB*HW];                  // 1 MB
__device__ float d_edge_part[NSPLIT][BB*HW];     // 8 MB partial channel-sums
__device__ float d_g[4][BB*HW];                  // 4 MB (symmetric taps)
__device__ float d_tmp[(size_t)BB*CHW];          // 64 MB horizontal-pass result
__device__ unsigned int d_minmax[2*BB];          // per-batch {min,max} uint bits

__global__ void init_minmax_kernel() {
    int i = threadIdx.x;
    if (i < BB) {
        d_minmax[2*i]   = 0x7f800000u; // +inf
        d_minmax[2*i+1] = 0u;          // 0
    }
}

// Partial Sobel edge-energy sums over 8 channels per block.
// Block (64,4): 8-row x 256-col tile; each thread owns 2 output rows x 4 cols.
__global__ __launch_bounds__(256) void edge_partial_kernel(const float* __restrict__ x) {
    __shared__ float xs[10][264];   // rows h0-1..h0+8; data cols [4..259], zero halo [3],[260]

    const int tx = threadIdx.x;     // 0..63 column quad
    const int ty = threadIdx.y;     // 0..3
    const int tid = ty*64 + tx;
    const int h0 = blockIdx.x*8;
    const int sp = blockIdx.y;      // channel split
    const int b  = blockIdx.z;

    if (tid < 10) { xs[tid][3] = 0.f; xs[tid][260] = 0.f; }

    const float* xb = x + (size_t)b*CHW + (size_t)sp*ECH*HW;
    float acc[2][4] = {};

    for (int c = 0; c < ECH; c++) {
        __syncthreads();
        // stage 10 rows x 64 quads = 640 tasks over 256 threads
        #pragma unroll
        for (int k = 0; k < 3; k++) {
            int i = tid + k*256;
            if (i < 640) {
                int r = i >> 6, q = i & 63;
                int gh = h0 - 1 + r;
                float4 v = make_float4(0.f, 0.f, 0.f, 0.f);
                if (gh >= 0 && gh < HH)
                    v = *(const float4*)(xb + (size_t)c*HW + gh*WW + q*4);
                *(float4*)&xs[r][4 + q*4] = v;
            }
        }
        __syncthreads();

        #pragma unroll
        for (int rr = 0; rr < 2; rr++) {
            const int base = ty + rr*4;       // local output row 0..7
            float d[3][4], s[3][4];
            #pragma unroll
            for (int r = 0; r < 3; r++) {
                const float* row = &xs[base + r][4 + 4*tx];
                float  l = row[-1];
                float4 m = *(const float4*)row;
                float rrr = row[4];
                d[r][0] = m.y - l;    s[r][0] = l   + 2.f*m.x + m.y;
                d[r][1] = m.z - m.x;  s[r][1] = m.x + 2.f*m.y + m.z;
                d[r][2] = m.w - m.y;  s[r][2] = m.y + 2.f*m.z + m.w;
                d[r][3] = rrr - m.z;  s[r][3] = m.z + 2.f*m.w + rrr;
            }
            #pragma unroll
            for (int j = 0; j < 4; j++) {
                float gx = d[0][j] + 2.f*d[1][j] + d[2][j];
                float gy = s[2][j] - s[0][j];
                acc[rr][j] = fmaf(gx, gx, acc[rr][j]);
                acc[rr][j] = fmaf(gy, gy, acc[rr][j]);
            }
        }
    }

    #pragma unroll
    for (int rr = 0; rr < 2; rr++) {
        const int h = h0 + ty + rr*4;
        float4 e = make_float4(acc[rr][0], acc[rr][1], acc[rr][2], acc[rr][3]);
        *(float4*)(d_edge_part[sp] + b*HW + h*WW + 4*tx) = e;
    }
}

// Sum partials -> edge; per-batch min/max via block reduce + uint atomics.
__global__ __launch_bounds__(256) void edge_reduce_kernel() {
    __shared__ float smin[8], smax[8];
    const int idx4 = blockIdx.x*256 + threadIdx.x;  // float4 index; block within one batch
    const int b = idx4 >> 14;                        // HW/4 = 16384 per batch

    float4 s = make_float4(0.f, 0.f, 0.f, 0.f);
    #pragma unroll
    for (int sp = 0; sp < NSPLIT; sp++) {
        float4 v = *(const float4*)(d_edge_part[sp] + (size_t)idx4*4);
        s.x += v.x; s.y += v.y; s.z += v.z; s.w += v.w;
    }
    s.x *= (1.f/64.f); s.y *= (1.f/64.f); s.z *= (1.f/64.f); s.w *= (1.f/64.f);
    *(float4*)(d_edge + (size_t)idx4*4) = s;

    float vmin = fminf(fminf(s.x, s.y), fminf(s.z, s.w));
    float vmax = fmaxf(fmaxf(s.x, s.y), fmaxf(s.z, s.w));
    #pragma unroll
    for (int o = 16; o; o >>= 1) {
        vmin = fminf(vmin, __shfl_xor_sync(0xffffffffu, vmin, o));
        vmax = fmaxf(vmax, __shfl_xor_sync(0xffffffffu, vmax, o));
    }
    const int wid = threadIdx.x >> 5, lane = threadIdx.x & 31;
    if (lane == 0) { smin[wid] = vmin; smax[wid] = vmax; }
    __syncthreads();
    if (threadIdx.x == 0) {
        float m = smin[0], M = smax[0];
        #pragma unroll
        for (int i = 1; i < 8; i++) { m = fminf(m, smin[i]); M = fmaxf(M, smax[i]); }
        atomicMin(&d_minmax[2*b],   __float_as_uint(m));
        atomicMax(&d_minmax[2*b+1], __float_as_uint(M));
    }
}

// Per-pixel normalized Gaussian taps (symmetric: store 4 planes).
__global__ void gauss_kernel() {
    const int idx = blockIdx.x*blockDim.x + threadIdx.x;
    const int b = idx / HW;
    const float emin = __uint_as_float(d_minmax[2*b]);
    const float emax = __uint_as_float(d_minmax[2*b+1]);
    const float e = (d_edge[idx] - emin) / (emax + 1e-6f);
    const float s = SIGMA_MIN + (SIGMA_MAX - SIGMA_MIN)*e;
    const float inv = 0.5f / (s*s);
    const float w2 = __expf(-1.f*inv);
    const float w1 = __expf(-4.f*inv);
    const float w0 = __expf(-9.f*inv);
    const float r = 1.f / (2.f*(w0 + w1 + w2) + 1.f);
    d_g[0][idx] = w0*r;
    d_g[1][idx] = w1*r;
    d_g[2][idx] = w2*r;
    d_g[3][idx] = r;
}

// Horizontal pass: thread = 4 outputs x 8 channels; g in regs; no barriers.
__global__ __launch_bounds__(256) void hblur_kernel(const float* __restrict__ x) {
    const int tx = threadIdx.x;                 // 0..63
    const int h  = blockIdx.x*4 + threadIdx.y;
    const int c0 = blockIdx.y*BCH;
    const int b  = blockIdx.z;
    const int w4 = tx*4;
    const int pidx = b*HW + h*WW + w4;

    const float4 G0 = *(const float4*)&d_g[0][pidx];
    const float4 G1 = *(const float4*)&d_g[1][pidx];
    const float4 G2 = *(const float4*)&d_g[2][pidx];
    const float4 G3 = *(const float4*)&d_g[3][pidx];

    const float* xr = x     + (size_t)b*CHW + (size_t)c0*HW + h*WW + w4;
    float*       tr = d_tmp + (size_t)b*CHW + (size_t)c0*HW + h*WW + w4;
    const bool hasL = (tx > 0), hasR = (tx < 63);
    const float4 z4 = make_float4(0.f, 0.f, 0.f, 0.f);

    #pragma unroll 2
    for (int c = 0; c < BCH; c++) {
        const float* p = xr + (size_t)c*HW;
        float4 m  = *(const float4*)p;
        float4 lf = hasL ? *(const float4*)(p - 4) : z4;
        float4 rf = hasR ? *(const float4*)(p + 4) : z4;
        float v0=lf.y, v1=lf.z, v2=lf.w, v3=m.x, v4=m.y, v5=m.z, v6=m.w, v7=rf.x, v8=rf.y, v9=rf.z;
        float4 o;
        o.x = fmaf(G0.x, v0+v6, fmaf(G1.x, v1+v5, fmaf(G2.x, v2+v4, G3.x*v3)));
        o.y = fmaf(G0.y, v1+v7, fmaf(G1.y, v2+v6, fmaf(G2.y, v3+v5, G3.y*v4)));
        o.z = fmaf(G0.z, v2+v8, fmaf(G1.z, v3+v7, fmaf(G2.z, v4+v6, G3.z*v5)));
        o.w = fmaf(G0.w, v3+v9, fmaf(G1.w, v4+v8, fmaf(G2.w, v5+v7, G3.w*v6)));
        *(float4*)(tr + (size_t)c*HW) = o;
    }
}

// Vertical pass: thread = 4 outputs x 8 channels; 7 guarded row loads.
__global__ __launch_bounds__(256) void vblur_kernel(float* __restrict__ out) {
    const int tx = threadIdx.x;
    const int h  = blockIdx.x*4 + threadIdx.y;
    const int c0 = blockIdx.y*BCH;
    const int b  = blockIdx.z;
    const int w4 = tx*4;
    const int pidx = b*HW + h*WW + w4;

    const float4 G0 = *(const float4*)&d_g[0][pidx];
    const float4 G1 = *(const float4*)&d_g[1][pidx];
    const float4 G2 = *(const float4*)&d_g[2][pidx];
    const float4 G3 = *(const float4*)&d_g[3][pidx];

    const float* tp = d_tmp + (size_t)b*CHW + (size_t)c0*HW + h*WW + w4;
    float*       op = out   + (size_t)b*CHW + (size_t)c0*HW + h*WW + w4;

    const bool m1 = (h >= 1), m2 = (h >= 2), m3 = (h >= 3);
    const bool p1 = (h < HH-1), p2 = (h < HH-2), p3 = (h < HH-3);
    const float4 z4 = make_float4(0.f, 0.f, 0.f, 0.f);

    #pragma unroll 2
    for (int c = 0; c < BCH; c++) {
        const float* p = tp + (size_t)c*HW;
        float4 cm = *(const float4*)p;
        float4 u1 = m1 ? *(const float4*)(p -   WW) : z4;
        float4 d1 = p1 ? *(const float4*)(p +   WW) : z4;
        float4 u2 = m2 ? *(const float4*)(p - 2*WW) : z4;
        float4 d2 = p2 ? *(const float4*)(p + 2*WW) : z4;
        float4 u3 = m3 ? *(const float4*)(p - 3*WW) : z4;
        float4 d3 = p3 ? *(const float4*)(p + 3*WW) : z4;
        float4 o;
        o.x = fmaf(G0.x, u3.x+d3.x, fmaf(G1.x, u2.x+d2.x, fmaf(G2.x, u1.x+d1.x, G3.x*cm.x)));
        o.y = fmaf(G0.y, u3.y+d3.y, fmaf(G1.y, u2.y+d2.y, fmaf(G2.y, u1.y+d1.y, G3.y*cm.y)));
        o.z = fmaf(G0.z, u3.z+d3.z, fmaf(G1.z, u2.z+d2.z, fmaf(G2.z, u1.z+d1.z, G3.z*cm.z)));
        o.w = fmaf(G0.w, u3.w+d3.w, fmaf(G1.w, u2.w+d2.w, fmaf(G2.w, u1.w+d1.w, G3.w*cm.w)));
        *(float4*)(op + (size_t)c*HW) = o;
    }
}

extern "C" void kernel_launch(void* const* d_in, const int* in_sizes, int n_in,
                              void* d_out, int out_size) {
    const float* x = (const float*)d_in[0];
    float* out = (float*)d_out;

    init_minmax_kernel<<<1, 32>>>();

    edge_partial_kernel<<<dim3(HH/8, NSPLIT, BB), dim3(64, 4)>>>(x);

    edge_reduce_kernel<<<(BB*HW/4)/256, 256>>>();

    gauss_kernel<<<(BB*HW)/256, 256>>>();

    hblur_kernel<<<dim3(HH/4, CC/BCH, BB), dim3(64, 4)>>>(x);

    vblur_kernel<<<dim3(HH/4, CC/BCH, BB), dim3(64, 4)>>>(out);
}

// round 5
// speedup vs baseline: 1.8223x; 1.0743x over previous
#include <cuda_runtime.h>

#define BB 4
#define CC 64
#define HH 256
#define WW 256
#define HW (HH*WW)
#define CHW (CC*HW)

#define NSPLIT 8
#define ECH (CC/NSPLIT)   // 8 channels per edge block
#define SB 4              // channels staged per barrier pair in edge kernel
#define BCH 8             // channels per blur block

#define SIGMA_MIN 0.6f
#define SIGMA_MAX 1.2f

// Scratch (static device allocations — no cudaMalloc allowed)
__device__ float d_edge[BB*HW];                  // 1 MB
__device__ float d_edge_part[NSPLIT][BB*HW];     // 8 MB partial channel-sums
__device__ float d_g[4][BB*HW];                  // 4 MB (symmetric taps)
__device__ float d_tmp[(size_t)BB*CHW];          // 64 MB horizontal-pass result
__device__ unsigned int d_minmax[2*BB];          // per-batch {min,max} uint bits

__global__ void init_minmax_kernel() {
    int i = threadIdx.x;
    if (i < BB) {
        d_minmax[2*i]   = 0x7f800000u; // +inf
        d_minmax[2*i+1] = 0u;          // 0
    }
}

// Partial Sobel edge-energy sums over 8 channels per block.
// Block (64,4): 8-row x 256-col tile; 4 channels staged per barrier pair.
__global__ __launch_bounds__(256) void edge_partial_kernel(const float* __restrict__ x) {
    __shared__ float xs[SB][10][264];   // [ch][row h0-1..h0+8][cols: data 4..259, zero halo 3,260]

    const int tx = threadIdx.x;     // 0..63 column quad
    const int ty = threadIdx.y;     // 0..3
    const int tid = ty*64 + tx;
    const int h0 = blockIdx.x*8;
    const int sp = blockIdx.y;      // channel split
    const int b  = blockIdx.z;

    // zero halo columns once (covered by first staging barrier)
    if (tid < SB*10) {
        int ch = tid / 10, r = tid % 10;
        xs[ch][r][3] = 0.f; xs[ch][r][260] = 0.f;
    }

    const float* xb = x + (size_t)b*CHW + (size_t)sp*ECH*HW;
    float acc[2][4] = {};

    for (int cb = 0; cb < ECH; cb += SB) {
        __syncthreads();
        // stage SB channels x 10 rows x 64 quads = 2560 quad tasks over 256 threads
        #pragma unroll
        for (int k = 0; k < 10; k++) {
            int i  = tid + k*256;
            int ch = i / 640;
            int rm = i - ch*640;
            int r  = rm >> 6, q = rm & 63;
            int gh = h0 - 1 + r;
            float4 v = make_float4(0.f, 0.f, 0.f, 0.f);
            if (gh >= 0 && gh < HH)
                v = *(const float4*)(xb + (size_t)(cb + ch)*HW + gh*WW + q*4);
            *(float4*)&xs[ch][r][4 + q*4] = v;
        }
        __syncthreads();

        #pragma unroll
        for (int ch = 0; ch < SB; ch++) {
            #pragma unroll
            for (int rr = 0; rr < 2; rr++) {
                const int base = ty + rr*4;       // local output row 0..7
                float d[3][4], s[3][4];
                #pragma unroll
                for (int r = 0; r < 3; r++) {
                    const float* row = &xs[ch][base + r][4 + 4*tx];
                    float  l = row[-1];
                    float4 m = *(const float4*)row;
                    float rt = row[4];
                    d[r][0] = m.y - l;    s[r][0] = l   + 2.f*m.x + m.y;
                    d[r][1] = m.z - m.x;  s[r][1] = m.x + 2.f*m.y + m.z;
                    d[r][2] = m.w - m.y;  s[r][2] = m.y + 2.f*m.z + m.w;
                    d[r][3] = rt  - m.z;  s[r][3] = m.z + 2.f*m.w + rt;
                }
                #pragma unroll
                for (int j = 0; j < 4; j++) {
                    float gx = d[0][j] + 2.f*d[1][j] + d[2][j];
                    float gy = s[2][j] - s[0][j];
                    acc[rr][j] = fmaf(gx, gx, acc[rr][j]);
                    acc[rr][j] = fmaf(gy, gy, acc[rr][j]);
                }
            }
        }
    }

    #pragma unroll
    for (int rr = 0; rr < 2; rr++) {
        const int h = h0 + ty + rr*4;
        float4 e = make_float4(acc[rr][0], acc[rr][1], acc[rr][2], acc[rr][3]);
        *(float4*)(d_edge_part[sp] + b*HW + h*WW + 4*tx) = e;
    }
}

// Sum partials -> edge; per-batch min/max via block reduce + uint atomics.
__global__ __launch_bounds__(256) void edge_reduce_kernel() {
    __shared__ float smin[8], smax[8];
    const int idx4 = blockIdx.x*256 + threadIdx.x;  // float4 index; block within one batch
    const int b = idx4 >> 14;                        // HW/4 = 16384 per batch

    float4 s = make_float4(0.f, 0.f, 0.f, 0.f);
    #pragma unroll
    for (int sp = 0; sp < NSPLIT; sp++) {
        float4 v = *(const float4*)(d_edge_part[sp] + (size_t)idx4*4);
        s.x += v.x; s.y += v.y; s.z += v.z; s.w += v.w;
    }
    s.x *= (1.f/64.f); s.y *= (1.f/64.f); s.z *= (1.f/64.f); s.w *= (1.f/64.f);
    *(float4*)(d_edge + (size_t)idx4*4) = s;

    float vmin = fminf(fminf(s.x, s.y), fminf(s.z, s.w));
    float vmax = fmaxf(fmaxf(s.x, s.y), fmaxf(s.z, s.w));
    #pragma unroll
    for (int o = 16; o; o >>= 1) {
        vmin = fminf(vmin, __shfl_xor_sync(0xffffffffu, vmin, o));
        vmax = fmaxf(vmax, __shfl_xor_sync(0xffffffffu, vmax, o));
    }
    const int wid = threadIdx.x >> 5, lane = threadIdx.x & 31;
    if (lane == 0) { smin[wid] = vmin; smax[wid] = vmax; }
    __syncthreads();
    if (threadIdx.x == 0) {
        float m = smin[0], M = smax[0];
        #pragma unroll
        for (int i = 1; i < 8; i++) { m = fminf(m, smin[i]); M = fmaxf(M, smax[i]); }
        atomicMin(&d_minmax[2*b],   __float_as_uint(m));
        atomicMax(&d_minmax[2*b+1], __float_as_uint(M));
    }
}

// Per-pixel normalized Gaussian taps. 1 expf per pixel: w1=w2^4, w0=w1^2*w2.
__global__ __launch_bounds__(128) void gauss_kernel() {
    const int idx4 = blockIdx.x*128 + threadIdx.x;   // float4 index
    const int b = idx4 >> 14;                         // HW/4 per batch
    const float emin = __uint_as_float(d_minmax[2*b]);
    const float rden = __fdividef(1.f, __uint_as_float(d_minmax[2*b+1]) + 1e-6f);

    float4 e4 = *(const float4*)(d_edge + (size_t)idx4*4);
    float4 o0, o1, o2, o3;
    float* ep = (float*)&e4;
    float* p0 = (float*)&o0; float* p1 = (float*)&o1;
    float* p2 = (float*)&o2; float* p3 = (float*)&o3;

    #pragma unroll
    for (int j = 0; j < 4; j++) {
        float e = (ep[j] - emin) * rden;
        float s = SIGMA_MIN + (SIGMA_MAX - SIGMA_MIN)*e;
        float t = __fdividef(1.f, s);
        float inv = 0.5f*t*t;
        float w2 = __expf(-inv);
        float w2_2 = w2*w2;
        float w1 = w2_2*w2_2;
        float w0 = w1*w1*w2;
        float r = __fdividef(1.f, 2.f*(w0 + w1 + w2) + 1.f);
        p0[j] = w0*r; p1[j] = w1*r; p2[j] = w2*r; p3[j] = r;
    }
    *(float4*)(d_g[0] + (size_t)idx4*4) = o0;
    *(float4*)(d_g[1] + (size_t)idx4*4) = o1;
    *(float4*)(d_g[2] + (size_t)idx4*4) = o2;
    *(float4*)(d_g[3] + (size_t)idx4*4) = o3;
}

// Horizontal pass: thread = 4 outputs x 8 channels; g in regs; no barriers.
__global__ __launch_bounds__(256) void hblur_kernel(const float* __restrict__ x) {
    const int tx = threadIdx.x;                 // 0..63
    const int h  = blockIdx.x*4 + threadIdx.y;
    const int c0 = blockIdx.y*BCH;
    const int b  = blockIdx.z;
    const int w4 = tx*4;
    const int pidx = b*HW + h*WW + w4;

    const float4 G0 = *(const float4*)&d_g[0][pidx];
    const float4 G1 = *(const float4*)&d_g[1][pidx];
    const float4 G2 = *(const float4*)&d_g[2][pidx];
    const float4 G3 = *(const float4*)&d_g[3][pidx];

    const float* xr = x     + (size_t)b*CHW + (size_t)c0*HW + h*WW + w4;
    float*       tr = d_tmp + (size_t)b*CHW + (size_t)c0*HW + h*WW + w4;
    const bool hasL = (tx > 0), hasR = (tx < 63);
    const float4 z4 = make_float4(0.f, 0.f, 0.f, 0.f);

    #pragma unroll 2
    for (int c = 0; c < BCH; c++) {
        const float* p = xr + (size_t)c*HW;
        float4 m  = *(const float4*)p;
        float4 lf = hasL ? *(const float4*)(p - 4) : z4;
        float4 rf = hasR ? *(const float4*)(p + 4) : z4;
        float v0=lf.y, v1=lf.z, v2=lf.w, v3=m.x, v4=m.y, v5=m.z, v6=m.w, v7=rf.x, v8=rf.y, v9=rf.z;
        float4 o;
        o.x = fmaf(G0.x, v0+v6, fmaf(G1.x, v1+v5, fmaf(G2.x, v2+v4, G3.x*v3)));
        o.y = fmaf(G0.y, v1+v7, fmaf(G1.y, v2+v6, fmaf(G2.y, v3+v5, G3.y*v4)));
        o.z = fmaf(G0.z, v2+v8, fmaf(G1.z, v3+v7, fmaf(G2.z, v4+v6, G3.z*v5)));
        o.w = fmaf(G0.w, v3+v9, fmaf(G1.w, v4+v8, fmaf(G2.w, v5+v7, G3.w*v6)));
        *(float4*)(tr + (size_t)c*HW) = o;
    }
}

// Vertical pass: thread = 4 outputs x 8 channels; 7 guarded row loads.
__global__ __launch_bounds__(256) void vblur_kernel(float* __restrict__ out) {
    const int tx = threadIdx.x;
    const int h  = blockIdx.x*4 + threadIdx.y;
    const int c0 = blockIdx.y*BCH;
    const int b  = blockIdx.z;
    const int w4 = tx*4;
    const int pidx = b*HW + h*WW + w4;

    const float4 G0 = *(const float4*)&d_g[0][pidx];
    const float4 G1 = *(const float4*)&d_g[1][pidx];
    const float4 G2 = *(const float4*)&d_g[2][pidx];
    const float4 G3 = *(const float4*)&d_g[3][pidx];

    const float* tp = d_tmp + (size_t)b*CHW + (size_t)c0*HW + h*WW + w4;
    float*       op = out   + (size_t)b*CHW + (size_t)c0*HW + h*WW + w4;

    const bool m1 = (h >= 1), m2 = (h >= 2), m3 = (h >= 3);
    const bool p1 = (h < HH-1), p2 = (h < HH-2), p3 = (h < HH-3);
    const float4 z4 = make_float4(0.f, 0.f, 0.f, 0.f);

    #pragma unroll 2
    for (int c = 0; c < BCH; c++) {
        const float* p = tp + (size_t)c*HW;
        float4 cm = *(const float4*)p;
        float4 u1 = m1 ? *(const float4*)(p -   WW) : z4;
        float4 d1 = p1 ? *(const float4*)(p +   WW) : z4;
        float4 u2 = m2 ? *(const float4*)(p - 2*WW) : z4;
        float4 d2 = p2 ? *(const float4*)(p + 2*WW) : z4;
        float4 u3 = m3 ? *(const float4*)(p - 3*WW) : z4;
        float4 d3 = p3 ? *(const float4*)(p + 3*WW) : z4;
        float4 o;
        o.x = fmaf(G0.x, u3.x+d3.x, fmaf(G1.x, u2.x+d2.x, fmaf(G2.x, u1.x+d1.x, G3.x*cm.x)));
        o.y = fmaf(G0.y, u3.y+d3.y, fmaf(G1.y, u2.y+d2.y, fmaf(G2.y, u1.y+d1.y, G3.y*cm.y)));
        o.z = fmaf(G0.z, u3.z+d3.z, fmaf(G1.z, u2.z+d2.z, fmaf(G2.z, u1.z+d1.z, G3.z*cm.z)));
        o.w = fmaf(G0.w, u3.w+d3.w, fmaf(G1.w, u2.w+d2.w, fmaf(G2.w, u1.w+d1.w, G3.w*cm.w)));
        *(float4*)(op + (size_t)c*HW) = o;
    }
}

extern "C" void kernel_launch(void* const* d_in, const int* in_sizes, int n_in,
                              void* d_out, int out_size) {
    const float* x = (const float*)d_in[0];
    float* out = (float*)d_out;

    init_minmax_kernel<<<1, 32>>>();

    edge_partial_kernel<<<dim3(HH/8, NSPLIT, BB), dim3(64, 4)>>>(x);

    edge_reduce_kernel<<<(BB*HW/4)/256, 256>>>();

    gauss_kernel<<<(BB*HW/4)/128, 128>>>();

    hblur_kernel<<<dim3(HH/4, CC/BCH, BB), dim3(64, 4)>>>(x);

    vblur_kernel<<<dim3(HH/4, CC/BCH, BB), dim3(64, 4)>>>(out);
}